// round 4
// baseline (speedup 1.0000x reference)
#include <cuda_runtime.h>
#include <cuda_bf16.h>

// Problem constants
#define BB 8
#define CC 512
#define OO 512
#define HH 32
#define WW 32
// GEMM tiling
#define MT 128
#define NT 128
#define KT 32
#define KDIM 2048  // C*4 taps

// Scratch (device globals; no allocation allowed)
__device__ float g_s[BB * CC];          // style modulation s[b][c]
__device__ float g_d[BB * OO];          // demod d[b][o]
__device__ float g_w2t[CC * OO];        // sum of squared 3x3 weights, [c][o]
__device__ float g_Wt[4 * KDIM * OO];   // phase-combined 2x2 weights, [ph][c*4+p*2+q][o]

// ---------------------------------------------------------------------------
// s[b][c] = fc_b[c] + sum_k style[b][k] * fc_w[c][k]
__global__ void k_style(const float* __restrict__ style,
                        const float* __restrict__ fc_w,
                        const float* __restrict__ fc_b) {
    int gid = blockIdx.x * blockDim.x + threadIdx.x;  // 4096 threads
    int b = gid >> 9, c = gid & 511;
    const float* srow = style + b * 512;
    const float* wrow = fc_w + c * 512;
    float acc = fc_b[c];
#pragma unroll 8
    for (int k = 0; k < 512; k++) acc += srow[k] * wrow[k];
    g_s[gid] = acc;
}

// ---------------------------------------------------------------------------
// Per (o,c): w2 = sum of squares; phase-combined 2x2 weights.
// Row groups (row-phase a): a=0: p0={dy0}, p1={dy1,dy2}; a=1: p0={dy0,dy1}, p1={dy2}
// Col groups (col-phase bb): symmetric.
__global__ void k_weights(const float* __restrict__ conv_w) {
    int gid = blockIdx.x * blockDim.x + threadIdx.x;  // 262144 threads
    int c = gid >> 9, o = gid & 511;
    const float* wp = conv_w + (size_t)(o * 512 + c) * 9;
    float w[9];
    float w2 = 0.f;
#pragma unroll
    for (int t = 0; t < 9; t++) { w[t] = wp[t]; w2 += w[t] * w[t]; }
    g_w2t[c * 512 + o] = w2;

    // r[a][p][dx] = combined row weight
    float r[2][2][3];
#pragma unroll
    for (int dx = 0; dx < 3; dx++) {
        r[0][0][dx] = w[0 + dx];
        r[0][1][dx] = w[3 + dx] + w[6 + dx];
        r[1][0][dx] = w[0 + dx] + w[3 + dx];
        r[1][1][dx] = w[6 + dx];
    }
#pragma unroll
    for (int a = 0; a < 2; a++)
#pragma unroll
        for (int pb = 0; pb < 2; pb++)
#pragma unroll
            for (int p = 0; p < 2; p++)
#pragma unroll
                for (int q = 0; q < 2; q++) {
                    float v;
                    if (pb == 0) v = (q == 0) ? r[a][p][0] : (r[a][p][1] + r[a][p][2]);
                    else         v = (q == 0) ? (r[a][p][0] + r[a][p][1]) : r[a][p][2];
                    int ph = a * 2 + pb;
                    g_Wt[((size_t)ph * KDIM + c * 4 + p * 2 + q) * 512 + o] = v;
                }
}

// ---------------------------------------------------------------------------
// d[b][o] = rsqrt(sum_c w2[o][c]*(1+s[b][c])^2 + 1e-8)
__global__ void k_demod() {
    int gid = blockIdx.x * blockDim.x + threadIdx.x;  // 4096
    int b = gid >> 9, o = gid & 511;
    const float* sb = g_s + b * 512;
    float acc = 1e-8f;
#pragma unroll 4
    for (int c = 0; c < 512; c++) {
        float t = 1.f + sb[c];
        acc += g_w2t[c * 512 + o] * t * t;
    }
    g_d[gid] = rsqrtf(acc);
}

// ---------------------------------------------------------------------------
// Main conv as GEMM per (batch, phase): M=512 (o), N=1024 (32x32 phase pixels),
// K=2048 (c * 4 taps). Modulation (1+s) folded into B-tile load; demod, bias,
// noise, leaky-relu in epilogue. Gather offsets hoisted; global loads for the
// NEXT K-tile are register-staged before computing the current one so memory
// latency overlaps the FMA burst.
__global__ void __launch_bounds__(256, 2)
k_conv(const float* __restrict__ x, const float* __restrict__ noise,
       const float* __restrict__ bias, float* __restrict__ out) {
    __shared__ float As[KT][MT];
    __shared__ float Bs[KT][NT];

    int z = blockIdx.z;           // 32 = b*4 + phase
    int b = z >> 2, ph = z & 3;
    int pa = ph >> 1, pb = ph & 1;
    int m0 = blockIdx.y * MT;     // o tile
    int n0 = blockIdx.x * NT;     // pixel tile
    int tid = threadIdx.x;

    const float* Wt = g_Wt + (size_t)ph * KDIM * 512;
    const float* xb = x + (size_t)b * CC * (HH * WW);
    const float* sb = g_s + b * 512;

    // compute-thread mapping: lanes sweep n (coalesced epilogue stores)
    int mi = (tid >> 4) * 8;
    int ni = (tid & 15) * 8;

    // A-load thread mapping (fixed across tiles): 4 float4 rows per thread
    int ak = tid >> 5;            // base k row (0..7), +8 per r
    int am4 = (tid & 31) * 4;

    // B-load thread mapping: n constant per thread across r
    int t7 = tid >> 7;          // 0 or 1
    int nb = tid & 127;         // B column this thread fills
    int bi = (n0 + nb) >> 5;    // phase-pixel row i
    int bj = (n0 + nb) & 31;    // phase-pixel col j

    // Hoisted per-r gather state: spatial offset, validity.
    int   goff[16];             // (row<<5)+col within a channel plane
    unsigned gvalid = 0;        // bit r = in-bounds
#pragma unroll
    for (int r = 0; r < 16; r++) {
        int kl = 2 * r + t7;            // k within tile, 0..31
        int p = (kl >> 1) & 1, q = kl & 1;
        int row = bi + p + pa - 1;
        int col = bj + q + pb - 1;
        goff[r] = (row << 5) + col;
        if ((unsigned)row < 32u && (unsigned)col < 32u) gvalid |= (1u << r);
    }

    float acc[8][8];
#pragma unroll
    for (int i = 0; i < 8; i++)
#pragma unroll
        for (int j = 0; j < 8; j++) acc[i][j] = 0.f;

    float4 aReg[4];
    float  bReg[16];

    // --- prologue: fetch tile 0 into registers ---
#pragma unroll
    for (int r = 0; r < 4; r++)
        aReg[r] = *(const float4*)&Wt[(size_t)(ak + 8 * r) * 512 + m0 + am4];
#pragma unroll
    for (int r = 0; r < 16; r++) {
        int kl = 2 * r + t7;
        int c = (kl >> 2);
        float v = 0.f;
        if (gvalid & (1u << r)) v = xb[(c << 10) + goff[r]] * (1.f + sb[c]);
        bReg[r] = v;
    }

    for (int k0 = 0; k0 < KDIM; k0 += KT) {
        // commit staged registers to smem
#pragma unroll
        for (int r = 0; r < 4; r++)
            *(float4*)&As[ak + 8 * r][am4] = aReg[r];
#pragma unroll
        for (int r = 0; r < 16; r++)
            Bs[2 * r + t7][nb] = bReg[r];
        __syncthreads();

        // stage NEXT tile's global loads (latency overlaps compute below)
        if (k0 + KT < KDIM) {
            int kn = k0 + KT;
            int cb = kn >> 2;
#pragma unroll
            for (int r = 0; r < 4; r++)
                aReg[r] = *(const float4*)&Wt[(size_t)(kn + ak + 8 * r) * 512 + m0 + am4];
#pragma unroll
            for (int r = 0; r < 16; r++) {
                int kl = 2 * r + t7;
                int c = cb + (kl >> 2);
                float v = 0.f;
                if (gvalid & (1u << r)) v = xb[(c << 10) + goff[r]] * (1.f + sb[c]);
                bReg[r] = v;
            }
        }

        // compute on current smem tile
#pragma unroll
        for (int k = 0; k < KT; k++) {
            float af[8], bf[8];
            *(float4*)&af[0] = *(float4*)&As[k][mi];
            *(float4*)&af[4] = *(float4*)&As[k][mi + 4];
            *(float4*)&bf[0] = *(float4*)&Bs[k][ni];
            *(float4*)&bf[4] = *(float4*)&Bs[k][ni + 4];
#pragma unroll
            for (int oi = 0; oi < 8; oi++)
#pragma unroll
                for (int nj = 0; nj < 8; nj++)
                    acc[oi][nj] += af[oi] * bf[nj];
        }
        __syncthreads();
    }

    // Epilogue: demod + bias + noise + leaky relu; scatter to strided phase grid
    const float* nz = noise + (size_t)b * (64 * 64);
#pragma unroll
    for (int oi = 0; oi < 8; oi++) {
        int o = m0 + mi + oi;
        float dd = g_d[b * 512 + o];
        float bo = bias[o];
        float* obase = out + ((size_t)(b * 512 + o) * 64) * 64;
#pragma unroll
        for (int nj = 0; nj < 8; nj++) {
            int nn = n0 + ni + nj;
            int i = nn >> 5, j = nn & 31;
            int Y = 2 * i + pa, X = 2 * j + pb;
            float v = dd * acc[oi][nj] + bo + nz[Y * 64 + X];
            v = (v > 0.f) ? v : 0.2f * v;
            obase[Y * 64 + X] = v;
        }
    }
}

// ---------------------------------------------------------------------------
extern "C" void kernel_launch(void* const* d_in, const int* in_sizes, int n_in,
                              void* d_out, int out_size) {
    const float* x      = (const float*)d_in[0];
    const float* style  = (const float*)d_in[1];
    const float* noise  = (const float*)d_in[2];
    const float* conv_w = (const float*)d_in[3];
    const float* fc_w   = (const float*)d_in[4];
    const float* fc_b   = (const float*)d_in[5];
    const float* bias   = (const float*)d_in[6];
    float* out = (float*)d_out;

    k_style<<<16, 256>>>(style, fc_w, fc_b);
    k_weights<<<1024, 256>>>(conv_w);
    k_demod<<<16, 256>>>();
    dim3 grid(8, 4, BB * 4);
    k_conv<<<grid, 256>>>(x, noise, bias, out);
}

// round 8
// speedup vs baseline: 2.2770x; 2.2770x over previous
#include <cuda_runtime.h>
#include <cuda_fp16.h>
#include <cstdint>

// Problem constants
#define BB 8
#define CC 512
#define OO 512

// Scratch (device globals; no allocation allowed)
__device__ float g_s[BB * CC];              // style modulation s[b][c]
__device__ float g_d[BB * OO];              // demod d[b][o]
__device__ float g_w2t[CC * OO];            // sum sq weights, [c][o]
__device__ uint32_t g_Wh32[4 * 1024 * 512]; // phase weights hi pairs [ph][k2][o]
__device__ uint32_t g_Wl32[4 * 1024 * 512]; // phase weights lo pairs

// ---------------------------------------------------------------------------
__device__ __forceinline__ uint32_t smem_u32(const void* p) {
    uint32_t a;
    asm("{ .reg .u64 t; cvta.to.shared.u64 t, %1; cvt.u32.u64 %0, t; }" : "=r"(a) : "l"(p));
    return a;
}
__device__ __forceinline__ void hsplit2(float v0, float v1, uint32_t& hi, uint32_t& lo) {
    __half2 h = __floats2half2_rn(v0, v1);
    float r0 = v0 - __low2float(h);
    float r1 = v1 - __high2float(h);
    __half2 l = __floats2half2_rn(r0, r1);
    hi = *reinterpret_cast<uint32_t*>(&h);
    lo = *reinterpret_cast<uint32_t*>(&l);
}
__device__ __forceinline__ void mma16816(float* d, const uint32_t* a,
                                         uint32_t b0, uint32_t b1) {
    asm volatile(
        "mma.sync.aligned.m16n8k16.row.col.f32.f16.f16.f32 "
        "{%0,%1,%2,%3}, {%4,%5,%6,%7}, {%8,%9}, {%0,%1,%2,%3};"
        : "+f"(d[0]), "+f"(d[1]), "+f"(d[2]), "+f"(d[3])
        : "r"(a[0]), "r"(a[1]), "r"(a[2]), "r"(a[3]), "r"(b0), "r"(b1));
}
__device__ __forceinline__ void cpa16(uint32_t dst, const void* src) {
    asm volatile("cp.async.ca.shared.global [%0], [%1], 16;" :: "r"(dst), "l"(src));
}
#define CPA_COMMIT asm volatile("cp.async.commit_group;" ::: "memory")
#define CPA_WAIT0  asm volatile("cp.async.wait_group 0;" ::: "memory")

// ---------------------------------------------------------------------------
// s[b][c] = fc_b[c] + sum_k style[b][k] * fc_w[c][k]
__global__ void k_style(const float* __restrict__ style,
                        const float* __restrict__ fc_w,
                        const float* __restrict__ fc_b) {
    int gid = blockIdx.x * blockDim.x + threadIdx.x;
    int b = gid >> 9, c = gid & 511;
    const float* srow = style + b * 512;
    const float* wrow = fc_w + c * 512;
    float acc = fc_b[c];
#pragma unroll 8
    for (int k = 0; k < 512; k++) acc += srow[k] * wrow[k];
    g_s[gid] = acc;
}

// ---------------------------------------------------------------------------
// Per (o,c): w2 = sum of squares; phase-combined 2x2 weights as fp16 hi/lo
// pairs in layout [ph][k2][o], k2 = c*2 + p (pair over q).
__global__ void k_weights(const float* __restrict__ conv_w) {
    int gid = blockIdx.x * blockDim.x + threadIdx.x;  // 262144
    int c = gid >> 9, o = gid & 511;                  // o fast -> coalesced writes
    const float* wp = conv_w + (size_t)(o * 512 + c) * 9;
    float w[9];
    float w2 = 0.f;
#pragma unroll
    for (int t = 0; t < 9; t++) { w[t] = wp[t]; w2 += w[t] * w[t]; }
    g_w2t[c * 512 + o] = w2;

    float r[2][2][3];
#pragma unroll
    for (int dx = 0; dx < 3; dx++) {
        r[0][0][dx] = w[0 + dx];
        r[0][1][dx] = w[3 + dx] + w[6 + dx];
        r[1][0][dx] = w[0 + dx] + w[3 + dx];
        r[1][1][dx] = w[6 + dx];
    }
#pragma unroll
    for (int a = 0; a < 2; a++)
#pragma unroll
        for (int pb = 0; pb < 2; pb++) {
            int ph = a * 2 + pb;
            float val[4];
#pragma unroll
            for (int p = 0; p < 2; p++)
#pragma unroll
                for (int q = 0; q < 2; q++) {
                    float v;
                    if (pb == 0) v = (q == 0) ? r[a][p][0] : (r[a][p][1] + r[a][p][2]);
                    else         v = (q == 0) ? (r[a][p][0] + r[a][p][1]) : r[a][p][2];
                    val[p * 2 + q] = v;
                }
            uint32_t h01, l01, h23, l23;
            hsplit2(val[0], val[1], h01, l01);
            hsplit2(val[2], val[3], h23, l23);
            size_t base = ((size_t)ph * 1024 + c * 2) * 512 + o;
            g_Wh32[base] = h01;  g_Wh32[base + 512] = h23;
            g_Wl32[base] = l01;  g_Wl32[base + 512] = l23;
        }
}

// ---------------------------------------------------------------------------
// d[b][o] = rsqrt(sum_c w2[o][c]*(1+s[b][c])^2 + 1e-8)
__global__ void k_demod() {
    int gid = blockIdx.x * blockDim.x + threadIdx.x;
    int b = gid >> 9, o = gid & 511;
    const float* sb = g_s + b * 512;
    float acc = 1e-8f;
#pragma unroll 4
    for (int c = 0; c < 512; c++) {
        float t = 1.f + sb[c];
        acc += g_w2t[c * 512 + o] * t * t;
    }
    g_d[gid] = rsqrtf(acc);
}

// ---------------------------------------------------------------------------
// Main GEMM on mma.sync (HMMA fp16, fp32 accum, 3-term hi/lo split).
// Per CTA: M=128 (o), N=128 pixels of one (b,phase), K=2048.
// grid = (8 ntiles, 4 mtiles, 32 b*ph), 256 threads = 8 warps (4m x 2n).
#define STRIDE 136          // uint32 row stride (136 % 32 == 8 -> conflict-free frags)
#define AHO 0
#define ALO (16 * STRIDE)       // 2176
#define BHO (32 * STRIDE)       // 4352
#define BLO (48 * STRIDE)       // 6528
#define STGU (64 * STRIDE)      // 8704 uint32 per stage
#define SMEM_BYTES (2 * STGU * 4)

__global__ void __launch_bounds__(256, 2)
k_mma(const float* __restrict__ x, const float* __restrict__ noise,
      const float* __restrict__ bias, float* __restrict__ out) {
    extern __shared__ uint32_t sm32[];
    uint32_t sb = smem_u32(sm32);
    int tid = threadIdx.x;
    int lane = tid & 31, wid = tid >> 5;

    int z = blockIdx.z;
    int b = z >> 2, ph = z & 3;
    int pa = ph >> 1, pbp = ph & 1;
    int nt = blockIdx.x;
    int o0 = blockIdx.y * 128;

    const float* xb = x + (size_t)b * 512 * 1024;
    const float* sv = g_s + b * 512;
    const uint32_t* Wh = g_Wh32 + (size_t)ph * 1024 * 512;
    const uint32_t* Wl = g_Wl32 + (size_t)ph * 1024 * 512;

    // B-gather mapping: thread -> pixel n, k2-half
    int n = tid & 127, half = tid >> 7;
    int np = nt * 128 + n, i = np >> 5, jc = np & 31;
    int cL = jc + pbp - 1, cR = cL + 1;
    bool vL = (unsigned)cL < 32u, vR = (unsigned)cR < 32u;
    int r0 = i + pa - 1, r1 = r0 + 1;
    bool v0r = (unsigned)r0 < 32u, v1r = (unsigned)r1 < 32u;
    int go0 = r0 << 5, go1 = r1 << 5;

    float acc[2][8][4];
#pragma unroll
    for (int mt = 0; mt < 2; mt++)
#pragma unroll
        for (int j = 0; j < 8; j++)
#pragma unroll
            for (int q = 0; q < 4; q++) acc[mt][j][q] = 0.f;

    float bReg[16];

#define LDG_B(chn) do { \
    int c0ch = (chn) * 8; \
    _Pragma("unroll") \
    for (int u = 0; u < 8; u++) { \
        int k2l = half * 8 + u; \
        int c = c0ch + (k2l >> 1); \
        float smv = 1.f + sv[c]; \
        const float* xp = xb + (c << 10) + ((k2l & 1) ? go1 : go0); \
        bool rv = (k2l & 1) ? v1r : v0r; \
        bReg[2 * u]     = (rv && vL) ? xp[cL] * smv : 0.f; \
        bReg[2 * u + 1] = (rv && vR) ? xp[cR] * smv : 0.f; \
    } } while (0)

#define CPA_A(chn, son) do { \
    _Pragma("unroll") \
    for (int r = 0; r < 2; r++) { \
        int idx = r * 256 + tid; \
        int k2 = idx >> 5, c16 = idx & 31; \
        const uint32_t* sh = Wh + (((size_t)((chn) * 16 + k2)) << 9) + o0 + c16 * 4; \
        const uint32_t* sl = Wl + (((size_t)((chn) * 16 + k2)) << 9) + o0 + c16 * 4; \
        uint32_t dd_ = k2 * STRIDE + c16 * 4; \
        cpa16(sb + ((son) + AHO + dd_) * 4, sh); \
        cpa16(sb + ((son) + ALO + dd_) * 4, sl); \
    } } while (0)

#define ST_B(son) do { \
    _Pragma("unroll") \
    for (int u = 0; u < 8; u++) { \
        int k2l = half * 8 + u; \
        uint32_t hi, lo; \
        hsplit2(bReg[2 * u], bReg[2 * u + 1], hi, lo); \
        sm32[(son) + BHO + k2l * STRIDE + n] = hi; \
        sm32[(son) + BLO + k2l * STRIDE + n] = lo; \
    } } while (0)

    // prologue: tile 0 into stage 0
    LDG_B(0);
    CPA_A(0, 0u);
    CPA_COMMIT;
    ST_B(0u);
    CPA_WAIT0;
    __syncthreads();

    int m_ = (wid & 3) * 32 + (lane >> 2);
    int n_ = (wid >> 2) * 64 + (lane >> 2);
    int kq = lane & 3;

    uint32_t so = 0;
    for (int ch = 0; ch < 64; ch++) {
        uint32_t son = so ^ STGU;
        if (ch < 63) {
            LDG_B(ch + 1);
            CPA_A(ch + 1, son);
            CPA_COMMIT;
        }

        // mma on stage so
#pragma unroll
        for (int ks = 0; ks < 2; ks++) {
            int kr = ks * 8 + kq;
            uint32_t ah[2][4], al[2][4];
#pragma unroll
            for (int mt = 0; mt < 2; mt++) {
                int m = m_ + mt * 16;
                uint32_t ra = so + AHO + kr * STRIDE;
                uint32_t rb = so + AHO + (kr + 4) * STRIDE;
                ah[mt][0] = sm32[ra + m];
                ah[mt][1] = sm32[ra + m + 8];
                ah[mt][2] = sm32[rb + m];
                ah[mt][3] = sm32[rb + m + 8];
                uint32_t rc = so + ALO + kr * STRIDE;
                uint32_t rd = so + ALO + (kr + 4) * STRIDE;
                al[mt][0] = sm32[rc + m];
                al[mt][1] = sm32[rc + m + 8];
                al[mt][2] = sm32[rd + m];
                al[mt][3] = sm32[rd + m + 8];
            }
#pragma unroll
            for (int j = 0; j < 8; j++) {
                int nn = n_ + 8 * j;
                uint32_t bh0 = sm32[so + BHO + kr * STRIDE + nn];
                uint32_t bh1 = sm32[so + BHO + (kr + 4) * STRIDE + nn];
                uint32_t bl0 = sm32[so + BLO + kr * STRIDE + nn];
                uint32_t bl1 = sm32[so + BLO + (kr + 4) * STRIDE + nn];
#pragma unroll
                for (int mt = 0; mt < 2; mt++) {
                    mma16816(acc[mt][j], ah[mt], bh0, bh1);
                    mma16816(acc[mt][j], ah[mt], bl0, bl1);
                    mma16816(acc[mt][j], al[mt], bh0, bh1);
                }
            }
        }

        if (ch < 63) ST_B(son);
        CPA_WAIT0;
        __syncthreads();
        so = son;
    }

    // Epilogue: demod + bias + noise + leaky relu, stride-2 phase scatter.
    const float* nz = noise + (size_t)b * 4096;
#pragma unroll
    for (int mt = 0; mt < 2; mt++) {
#pragma unroll
        for (int hh = 0; hh < 2; hh++) {
            int o = o0 + m_ + mt * 16 + hh * 8;
            float dd = g_d[b * 512 + o];
            float bo = bias[o];
            float* ob = out + (size_t)(b * 512 + o) * 4096;
#pragma unroll
            for (int j = 0; j < 8; j++) {
                int nc = (wid >> 2) * 64 + 8 * j + (lane & 3) * 2;
                int npx = nt * 128 + nc;
                int ii = npx >> 5, jj = npx & 31;
                int Y = 2 * ii + pa;
                int X0 = 2 * jj + pbp;
                float v0 = dd * acc[mt][j][hh * 2]     + bo + nz[Y * 64 + X0];
                float v1 = dd * acc[mt][j][hh * 2 + 1] + bo + nz[Y * 64 + X0 + 2];
                v0 = fmaxf(v0, 0.2f * v0);
                v1 = fmaxf(v1, 0.2f * v1);
                ob[Y * 64 + X0]     = v0;
                ob[Y * 64 + X0 + 2] = v1;
            }
        }
    }
}

// ---------------------------------------------------------------------------
extern "C" void kernel_launch(void* const* d_in, const int* in_sizes, int n_in,
                              void* d_out, int out_size) {
    const float* x      = (const float*)d_in[0];
    const float* style  = (const float*)d_in[1];
    const float* noise  = (const float*)d_in[2];
    const float* conv_w = (const float*)d_in[3];
    const float* fc_w   = (const float*)d_in[4];
    const float* fc_b   = (const float*)d_in[5];
    const float* bias   = (const float*)d_in[6];
    float* out = (float*)d_out;

    cudaFuncSetAttribute(k_mma, cudaFuncAttributeMaxDynamicSharedMemorySize,
                         SMEM_BYTES);

    k_style<<<16, 256>>>(style, fc_w, fc_b);
    k_weights<<<1024, 256>>>(conv_w);
    k_demod<<<16, 256>>>();
    dim3 grid(8, 4, 32);
    k_mma<<<grid, 256, SMEM_BYTES>>>(x, noise, bias, out);
}

// round 11
// speedup vs baseline: 3.2182x; 1.4134x over previous
#include <cuda_runtime.h>
#include <cuda_fp16.h>
#include <cstdint>

// Problem constants
#define BB 8
#define CC 512
#define OO 512

// Scratch (device globals; no allocation allowed)
__device__ float g_s[BB * CC];              // style modulation s[b][c]
__device__ float g_d[BB * OO];              // demod d[b][o]
__device__ float g_w2t[CC * OO];            // sum sq weights, [c][o]
__device__ uint32_t g_Wh32[4 * 1024 * 512]; // phase weights hi pairs [ph][k2][o]
__device__ uint32_t g_Wl32[4 * 1024 * 512]; // phase weights lo pairs
__device__ __half g_xmh[BB * CC * 1024];    // modulated input, fp16 [b][c][pix]

// ---------------------------------------------------------------------------
__device__ __forceinline__ uint32_t smem_u32(const void* p) {
    uint32_t a;
    asm("{ .reg .u64 t; cvta.to.shared.u64 t, %1; cvt.u32.u64 %0, t; }" : "=r"(a) : "l"(p));
    return a;
}
__device__ __forceinline__ void hsplit2(float v0, float v1, uint32_t& hi, uint32_t& lo) {
    __half2 h = __floats2half2_rn(v0, v1);
    float r0 = v0 - __low2float(h);
    float r1 = v1 - __high2float(h);
    __half2 l = __floats2half2_rn(r0, r1);
    hi = *reinterpret_cast<uint32_t*>(&h);
    lo = *reinterpret_cast<uint32_t*>(&l);
}
__device__ __forceinline__ void mma16816(float* d, const uint32_t* a,
                                         uint32_t b0, uint32_t b1) {
    asm volatile(
        "mma.sync.aligned.m16n8k16.row.col.f32.f16.f16.f32 "
        "{%0,%1,%2,%3}, {%4,%5,%6,%7}, {%8,%9}, {%0,%1,%2,%3};"
        : "+f"(d[0]), "+f"(d[1]), "+f"(d[2]), "+f"(d[3])
        : "r"(a[0]), "r"(a[1]), "r"(a[2]), "r"(a[3]), "r"(b0), "r"(b1));
}
__device__ __forceinline__ void cpa16(uint32_t dst, const void* src) {
    asm volatile("cp.async.ca.shared.global [%0], [%1], 16;" :: "r"(dst), "l"(src));
}
#define CPA_COMMIT asm volatile("cp.async.commit_group;" ::: "memory")
#define CPA_WAIT0  asm volatile("cp.async.wait_group 0;" ::: "memory")

// ---------------------------------------------------------------------------
// s[b][c] = fc_b[c] + sum_k style[b][k] * fc_w[c][k]
__global__ void k_style(const float* __restrict__ style,
                        const float* __restrict__ fc_w,
                        const float* __restrict__ fc_b) {
    int gid = blockIdx.x * blockDim.x + threadIdx.x;
    int b = gid >> 9, c = gid & 511;
    const float* srow = style + b * 512;
    const float* wrow = fc_w + c * 512;
    float acc = fc_b[c];
#pragma unroll 8
    for (int k = 0; k < 512; k++) acc += srow[k] * wrow[k];
    g_s[gid] = acc;
}

// ---------------------------------------------------------------------------
// xmh[b][c][pix] = fp16(x * (1+s))   (modulation folded into input, fp16)
__global__ void k_xprep(const float* __restrict__ x) {
    int gid = blockIdx.x * blockDim.x + threadIdx.x;  // 1,048,576: 4 pix each
    int pix4 = gid & 255;
    int bc = gid >> 8;                                // b*512 + c
    float s = 1.f + g_s[bc];
    float4 v = *(const float4*)&x[((size_t)bc << 10) + pix4 * 4];
    __half2 h01 = __floats2half2_rn(v.x * s, v.y * s);
    __half2 h23 = __floats2half2_rn(v.z * s, v.w * s);
    uint2 pk = make_uint2(*reinterpret_cast<uint32_t*>(&h01),
                          *reinterpret_cast<uint32_t*>(&h23));
    *(uint2*)&g_xmh[((size_t)bc << 10) + pix4 * 4] = pk;
}

// ---------------------------------------------------------------------------
// Per (o,c): w2 = sum of squares; phase-combined 2x2 weights as fp16 hi/lo
// pairs in layout [ph][k2][o], k2 = c*2 + p (pair over q).
__global__ void k_weights(const float* __restrict__ conv_w) {
    int gid = blockIdx.x * blockDim.x + threadIdx.x;  // 262144
    int c = gid >> 9, o = gid & 511;                  // o fast -> coalesced writes
    const float* wp = conv_w + (size_t)(o * 512 + c) * 9;
    float w[9];
    float w2 = 0.f;
#pragma unroll
    for (int t = 0; t < 9; t++) { w[t] = wp[t]; w2 += w[t] * w[t]; }
    g_w2t[c * 512 + o] = w2;

    float r[2][2][3];
#pragma unroll
    for (int dx = 0; dx < 3; dx++) {
        r[0][0][dx] = w[0 + dx];
        r[0][1][dx] = w[3 + dx] + w[6 + dx];
        r[1][0][dx] = w[0 + dx] + w[3 + dx];
        r[1][1][dx] = w[6 + dx];
    }
#pragma unroll
    for (int a = 0; a < 2; a++)
#pragma unroll
        for (int pb = 0; pb < 2; pb++) {
            int ph = a * 2 + pb;
            float val[4];
#pragma unroll
            for (int p = 0; p < 2; p++)
#pragma unroll
                for (int q = 0; q < 2; q++) {
                    float v;
                    if (pb == 0) v = (q == 0) ? r[a][p][0] : (r[a][p][1] + r[a][p][2]);
                    else         v = (q == 0) ? (r[a][p][0] + r[a][p][1]) : r[a][p][2];
                    val[p * 2 + q] = v;
                }
            uint32_t h01, l01, h23, l23;
            hsplit2(val[0], val[1], h01, l01);
            hsplit2(val[2], val[3], h23, l23);
            size_t base = ((size_t)ph * 1024 + c * 2) * 512 + o;
            g_Wh32[base] = h01;  g_Wh32[base + 512] = h23;
            g_Wl32[base] = l01;  g_Wl32[base + 512] = l23;
        }
}

// ---------------------------------------------------------------------------
// d[b][o] = rsqrt(sum_c w2[o][c]*(1+s[b][c])^2 + 1e-8)
__global__ void k_demod() {
    int gid = blockIdx.x * blockDim.x + threadIdx.x;
    int b = gid >> 9, o = gid & 511;
    const float* sb = g_s + b * 512;
    float acc = 1e-8f;
#pragma unroll 4
    for (int c = 0; c < 512; c++) {
        float t = 1.f + sb[c];
        acc += g_w2t[c * 512 + o] * t * t;
    }
    g_d[gid] = rsqrtf(acc);
}

// ---------------------------------------------------------------------------
// Main GEMM on mma.sync, 2-term split: (Ah + Al) x Bh, fp32 accum.
// A (hi+lo) streamed via cp.async; B gathered as fp16 from g_xmh (no split).
// Per CTA: M=128 (o), N=128 pixels of one (b,phase), K=2048.
// grid = (8 ntiles, 4 mtiles, 32 b*ph), 256 threads = 8 warps (4m x 2n).
#define STRIDE 136              // uint32 row stride (conflict-free frags)
#define AHO 0
#define ALO (16 * STRIDE)       // 2176
#define BHO (32 * STRIDE)       // 4352
#define STGU (48 * STRIDE)      // 6528 uint32 per stage
#define SMEM_BYTES (2 * STGU * 4)

__global__ void __launch_bounds__(256, 2)
k_mma(const float* __restrict__ noise,
      const float* __restrict__ bias, float* __restrict__ out) {
    extern __shared__ uint32_t sm32[];
    uint32_t sb = smem_u32(sm32);
    int tid = threadIdx.x;
    int lane = tid & 31, wid = tid >> 5;

    int z = blockIdx.z;
    int b = z >> 2, ph = z & 3;
    int pa = ph >> 1, pbp = ph & 1;
    int nt = blockIdx.x;
    int o0 = blockIdx.y * 128;

    const __half* xmb = g_xmh + ((size_t)b << 19);   // b*512*1024
    const uint32_t* Wh = g_Wh32 + (size_t)ph * 1024 * 512;
    const uint32_t* Wl = g_Wl32 + (size_t)ph * 1024 * 512;

    // B-gather mapping: thread -> pixel n, k2-half
    int n = tid & 127, half = tid >> 7;
    int np = nt * 128 + n, i = np >> 5, jc = np & 31;
    int cL = jc + pbp - 1, cR = cL + 1;
    bool vL = (unsigned)cL < 32u, vR = (unsigned)cR < 32u;
    int r0 = i + pa - 1, r1 = r0 + 1;
    bool v0r = (unsigned)r0 < 32u, v1r = (unsigned)r1 < 32u;
    int go0 = r0 << 5, go1 = r1 << 5;
    const __half hz = __ushort_as_half((unsigned short)0);

    float acc[2][8][4];
#pragma unroll
    for (int mt = 0; mt < 2; mt++)
#pragma unroll
        for (int j = 0; j < 8; j++)
#pragma unroll
            for (int q = 0; q < 4; q++) acc[mt][j][q] = 0.f;

    __half hq0[8], hq1[8];

#define LDG_B(chn) do { \
    int c0ch = (chn) * 8; \
    _Pragma("unroll") \
    for (int u = 0; u < 8; u++) { \
        int k2l = half * 8 + u; \
        int c = c0ch + (k2l >> 1); \
        const __half* xp = xmb + (c << 10) + ((k2l & 1) ? go1 : go0); \
        bool rv = (k2l & 1) ? v1r : v0r; \
        hq0[u] = (rv && vL) ? xp[cL] : hz; \
        hq1[u] = (rv && vR) ? xp[cR] : hz; \
    } } while (0)

#define CPA_A(chn, son) do { \
    _Pragma("unroll") \
    for (int r = 0; r < 2; r++) { \
        int idx = r * 256 + tid; \
        int k2 = idx >> 5, c16 = idx & 31; \
        const uint32_t* sh = Wh + (((size_t)((chn) * 16 + k2)) << 9) + o0 + c16 * 4; \
        const uint32_t* sl = Wl + (((size_t)((chn) * 16 + k2)) << 9) + o0 + c16 * 4; \
        uint32_t dd_ = k2 * STRIDE + c16 * 4; \
        cpa16(sb + ((son) + AHO + dd_) * 4, sh); \
        cpa16(sb + ((son) + ALO + dd_) * 4, sl); \
    } } while (0)

#define ST_B(son) do { \
    _Pragma("unroll") \
    for (int u = 0; u < 8; u++) { \
        int k2l = half * 8 + u; \
        __half2 pk = __halves2half2(hq0[u], hq1[u]); \
        sm32[(son) + BHO + k2l * STRIDE + n] = *reinterpret_cast<uint32_t*>(&pk); \
    } } while (0)

    // prologue: tile 0 into stage 0
    CPA_A(0, 0u);
    CPA_COMMIT;
    LDG_B(0);
    ST_B(0u);
    CPA_WAIT0;
    __syncthreads();

    int m_ = (wid & 3) * 32 + (lane >> 2);
    int n_ = (wid >> 2) * 64 + (lane >> 2);
    int kq = lane & 3;

    uint32_t so = 0;
    for (int ch = 0; ch < 64; ch++) {
        uint32_t son = so ^ STGU;
        if (ch < 63) {
            CPA_A(ch + 1, son);
            CPA_COMMIT;
            LDG_B(ch + 1);
        }

        // mma on stage so: (Ah + Al) x Bh
#pragma unroll
        for (int ks = 0; ks < 2; ks++) {
            int kr = ks * 8 + kq;
            uint32_t ah[2][4], al[2][4];
#pragma unroll
            for (int mt = 0; mt < 2; mt++) {
                int m = m_ + mt * 16;
                uint32_t ra = so + AHO + kr * STRIDE;
                uint32_t rb = so + AHO + (kr + 4) * STRIDE;
                ah[mt][0] = sm32[ra + m];
                ah[mt][1] = sm32[ra + m + 8];
                ah[mt][2] = sm32[rb + m];
                ah[mt][3] = sm32[rb + m + 8];
                uint32_t rc = so + ALO + kr * STRIDE;
                uint32_t rd = so + ALO + (kr + 4) * STRIDE;
                al[mt][0] = sm32[rc + m];
                al[mt][1] = sm32[rc + m + 8];
                al[mt][2] = sm32[rd + m];
                al[mt][3] = sm32[rd + m + 8];
            }
#pragma unroll
            for (int j = 0; j < 8; j++) {
                int nn = n_ + 8 * j;
                uint32_t bh0 = sm32[so + BHO + kr * STRIDE + nn];
                uint32_t bh1 = sm32[so + BHO + (kr + 4) * STRIDE + nn];
#pragma unroll
                for (int mt = 0; mt < 2; mt++) {
                    mma16816(acc[mt][j], ah[mt], bh0, bh1);
                    mma16816(acc[mt][j], al[mt], bh0, bh1);
                }
            }
        }

        if (ch < 63) ST_B(son);
        CPA_WAIT0;
        __syncthreads();
        so = son;
    }

    // Epilogue: demod + bias + noise + leaky relu, stride-2 phase scatter.
    const float* nz = noise + (size_t)b * 4096;
#pragma unroll
    for (int mt = 0; mt < 2; mt++) {
#pragma unroll
        for (int hh = 0; hh < 2; hh++) {
            int o = o0 + m_ + mt * 16 + hh * 8;
            float dd = g_d[b * 512 + o];
            float bo = bias[o];
            float* ob = out + (size_t)(b * 512 + o) * 4096;
#pragma unroll
            for (int j = 0; j < 8; j++) {
                int nc = (wid >> 2) * 64 + 8 * j + (lane & 3) * 2;
                int npx = nt * 128 + nc;
                int ii = npx >> 5, jj = npx & 31;
                int Y = 2 * ii + pa;
                int X0 = 2 * jj + pbp;
                float v0 = dd * acc[mt][j][hh * 2]     + bo + nz[Y * 64 + X0];
                float v1 = dd * acc[mt][j][hh * 2 + 1] + bo + nz[Y * 64 + X0 + 2];
                v0 = fmaxf(v0, 0.2f * v0);
                v1 = fmaxf(v1, 0.2f * v1);
                ob[Y * 64 + X0]     = v0;
                ob[Y * 64 + X0 + 2] = v1;
            }
        }
    }
}

// ---------------------------------------------------------------------------
extern "C" void kernel_launch(void* const* d_in, const int* in_sizes, int n_in,
                              void* d_out, int out_size) {
    const float* x      = (const float*)d_in[0];
    const float* style  = (const float*)d_in[1];
    const float* noise  = (const float*)d_in[2];
    const float* conv_w = (const float*)d_in[3];
    const float* fc_w   = (const float*)d_in[4];
    const float* fc_b   = (const float*)d_in[5];
    const float* bias   = (const float*)d_in[6];
    float* out = (float*)d_out;

    cudaFuncSetAttribute(k_mma, cudaFuncAttributeMaxDynamicSharedMemorySize,
                         SMEM_BYTES);

    k_style<<<16, 256>>>(style, fc_w, fc_b);
    k_weights<<<1024, 256>>>(conv_w);
    k_xprep<<<4096, 256>>>(x);
    k_demod<<<16, 256>>>();
    dim3 grid(8, 4, 32);
    k_mma<<<grid, 256, SMEM_BYTES>>>(noise, bias, out);
}

// round 12
// speedup vs baseline: 3.3769x; 1.0493x over previous
#include <cuda_runtime.h>
#include <cuda_fp16.h>
#include <cstdint>

// Problem constants
#define BB 8
#define CC 512
#define OO 512

// Scratch (device globals; no allocation allowed)
__device__ float g_s[BB * CC];              // style modulation s[b][c]
__device__ float g_d[BB * OO];              // demod d[b][o]
__device__ float g_w2t[CC * OO];            // sum sq weights, [c][o]
__device__ float g_part[16 * BB * OO];      // demod partials [cs][b][o]
__device__ uint32_t g_Wh32[4 * 1024 * 512]; // A hi, fragment-linear (see k_weights)
__device__ uint32_t g_Wl32[4 * 1024 * 512]; // A lo, fragment-linear
__device__ __half g_xmh[BB * CC * 1024];    // modulated input, fp16 [b][c][pix]

// ---------------------------------------------------------------------------
__device__ __forceinline__ uint32_t smem_u32(const void* p) {
    uint32_t a;
    asm("{ .reg .u64 t; cvta.to.shared.u64 t, %1; cvt.u32.u64 %0, t; }" : "=r"(a) : "l"(p));
    return a;
}
__device__ __forceinline__ void hsplit2(float v0, float v1, uint32_t& hi, uint32_t& lo) {
    __half2 h = __floats2half2_rn(v0, v1);
    float r0 = v0 - __low2float(h);
    float r1 = v1 - __high2float(h);
    __half2 l = __floats2half2_rn(r0, r1);
    hi = *reinterpret_cast<uint32_t*>(&h);
    lo = *reinterpret_cast<uint32_t*>(&l);
}
__device__ __forceinline__ void mma16816(float* d, const uint32_t* a,
                                         uint32_t b0, uint32_t b1) {
    asm volatile(
        "mma.sync.aligned.m16n8k16.row.col.f32.f16.f16.f32 "
        "{%0,%1,%2,%3}, {%4,%5,%6,%7}, {%8,%9}, {%0,%1,%2,%3};"
        : "+f"(d[0]), "+f"(d[1]), "+f"(d[2]), "+f"(d[3])
        : "r"(a[0]), "r"(a[1]), "r"(a[2]), "r"(a[3]), "r"(b0), "r"(b1));
}
__device__ __forceinline__ void cpa16(uint32_t dst, const void* src) {
    asm volatile("cp.async.ca.shared.global [%0], [%1], 16;" :: "r"(dst), "l"(src));
}
#define CPA_COMMIT asm volatile("cp.async.commit_group;" ::: "memory")
#define CPA_WAIT0  asm volatile("cp.async.wait_group 0;" ::: "memory")

// Fragment-linear A index: [ph][ot(4)][ch(64)][mw(4)][mt(2)][ks(2)][lane(32)][w(4)]
__device__ __forceinline__ size_t afrag_idx(int ph, int k2g, int o) {
    int ch = k2g >> 4, k2l = k2g & 15;
    int ot = o >> 7, om = o & 127;
    int mw = om >> 5, r32 = om & 31;
    int mt = r32 >> 4, r16 = r32 & 15;
    int wb = r16 >> 3, lrow = r16 & 7;
    int ks = k2l >> 3, k8 = k2l & 7;
    int kq = k8 & 3, wk = k8 >> 2;
    int lane = lrow * 4 + kq;
    int w = wk * 2 + wb;
    return ((((size_t)ph * 4 + ot) * 64 + ch) * 2048) +
           ((((mw * 2 + mt) * 2 + ks) * 32 + lane) * 4 + w);
}

// ---------------------------------------------------------------------------
// s[b][c] = fc_b[c] + sum_k style[b][k] * fc_w[c][k]
__global__ void k_style(const float* __restrict__ style,
                        const float* __restrict__ fc_w,
                        const float* __restrict__ fc_b) {
    int gid = blockIdx.x * blockDim.x + threadIdx.x;
    int b = gid >> 9, c = gid & 511;
    const float* srow = style + b * 512;
    const float* wrow = fc_w + c * 512;
    float acc = fc_b[c];
#pragma unroll 8
    for (int k = 0; k < 512; k++) acc += srow[k] * wrow[k];
    g_s[gid] = acc;
}

// ---------------------------------------------------------------------------
// xmh[b][c][pix] = fp16(x * (1+s))
__global__ void k_xprep(const float* __restrict__ x) {
    int gid = blockIdx.x * blockDim.x + threadIdx.x;  // 1,048,576: 4 pix each
    int pix4 = gid & 255;
    int bc = gid >> 8;
    float s = 1.f + g_s[bc];
    float4 v = *(const float4*)&x[((size_t)bc << 10) + pix4 * 4];
    __half2 h01 = __floats2half2_rn(v.x * s, v.y * s);
    __half2 h23 = __floats2half2_rn(v.z * s, v.w * s);
    uint2 pk = make_uint2(*reinterpret_cast<uint32_t*>(&h01),
                          *reinterpret_cast<uint32_t*>(&h23));
    *(uint2*)&g_xmh[((size_t)bc << 10) + pix4 * 4] = pk;
}

// ---------------------------------------------------------------------------
// Per (o,c): w2; phase-combined 2x2 weights as fp16 hi/lo written directly in
// mma-fragment-linear order (one LDS.128 per fragment in k_mma).
__global__ void k_weights(const float* __restrict__ conv_w) {
    int gid = blockIdx.x * blockDim.x + threadIdx.x;  // 262144
    int o = gid >> 9, c = gid & 511;                  // c fast -> dense reads
    const float* wp = conv_w + (size_t)(o * 512 + c) * 9;
    float w[9];
    float w2 = 0.f;
#pragma unroll
    for (int t = 0; t < 9; t++) { w[t] = wp[t]; w2 += w[t] * w[t]; }
    g_w2t[c * 512 + o] = w2;

    float r[2][2][3];
#pragma unroll
    for (int dx = 0; dx < 3; dx++) {
        r[0][0][dx] = w[0 + dx];
        r[0][1][dx] = w[3 + dx] + w[6 + dx];
        r[1][0][dx] = w[0 + dx] + w[3 + dx];
        r[1][1][dx] = w[6 + dx];
    }
#pragma unroll
    for (int a = 0; a < 2; a++)
#pragma unroll
        for (int pb = 0; pb < 2; pb++) {
            int ph = a * 2 + pb;
            float val[4];
#pragma unroll
            for (int p = 0; p < 2; p++)
#pragma unroll
                for (int q = 0; q < 2; q++) {
                    float v;
                    if (pb == 0) v = (q == 0) ? r[a][p][0] : (r[a][p][1] + r[a][p][2]);
                    else         v = (q == 0) ? (r[a][p][0] + r[a][p][1]) : r[a][p][2];
                    val[p * 2 + q] = v;
                }
            uint32_t h01, l01, h23, l23;
            hsplit2(val[0], val[1], h01, l01);
            hsplit2(val[2], val[3], h23, l23);
            size_t i0 = afrag_idx(ph, 2 * c, o);
            size_t i1 = afrag_idx(ph, 2 * c + 1, o);
            g_Wh32[i0] = h01;  g_Wh32[i1] = h23;
            g_Wl32[i0] = l01;  g_Wl32[i1] = l23;
        }
}

// ---------------------------------------------------------------------------
// Demod partials: block (cs, b), 512 threads (one per o); 32 c's per block.
__global__ void k_demod_acc() {
    int cs = blockIdx.x, b = blockIdx.y;
    int o = threadIdx.x;
    const float* sb = g_s + b * 512;
    float acc = 0.f;
#pragma unroll 8
    for (int u = 0; u < 32; u++) {
        int c = cs * 32 + u;
        float t = 1.f + sb[c];
        acc += g_w2t[c * 512 + o] * t * t;
    }
    g_part[(cs * BB + b) * 512 + o] = acc;
}
// d = rsqrt(sum partials + eps)
__global__ void k_fin() {
    int gid = blockIdx.x * blockDim.x + threadIdx.x;  // 4096: b*512+o
    int b = gid >> 9, o = gid & 511;
    float acc = 1e-8f;
#pragma unroll
    for (int cs = 0; cs < 16; cs++) acc += g_part[(cs * BB + b) * 512 + o];
    g_d[gid] = rsqrtf(acc);
}

// ---------------------------------------------------------------------------
// Main GEMM on mma.sync, 2-term split: (Ah + Al) x Bh, fp32 accum.
// A fragment-linear via cp.async (LDS.128 fragment loads); B gathered fp16.
#define AHO 0
#define ALO 2048
#define BHO 4096
#define BSTRIDE 136
#define STGU (BHO + 16 * BSTRIDE)   // 6272 u32 per stage
#define SMEM_BYTES (2 * STGU * 4)

__global__ void __launch_bounds__(256, 2)
k_mma(const float* __restrict__ noise,
      const float* __restrict__ bias, float* __restrict__ out) {
    extern __shared__ uint32_t sm32[];
    uint32_t sb = smem_u32(sm32);
    int tid = threadIdx.x;
    int lane = tid & 31, wid = tid >> 5;

    int z = blockIdx.z;
    int b = z >> 2, ph = z & 3;
    int pa = ph >> 1, pbp = ph & 1;
    int nt = blockIdx.x;
    int o0 = blockIdx.y * 128;

    const __half* xmb = g_xmh + ((size_t)b << 19);
    const uint32_t* WhF = g_Wh32 + (((size_t)ph * 4 + (o0 >> 7)) * 64) * 2048;
    const uint32_t* WlF = g_Wl32 + (((size_t)ph * 4 + (o0 >> 7)) * 64) * 2048;

    // B-gather mapping: thread -> pixel n, k2-half
    int n = tid & 127, half = tid >> 7;
    int np = nt * 128 + n, i = np >> 5, jc = np & 31;
    int cL = jc + pbp - 1, cR = cL + 1;
    bool vL = (unsigned)cL < 32u, vR = (unsigned)cR < 32u;
    int r0 = i + pa - 1, r1 = r0 + 1;
    bool v0r = (unsigned)r0 < 32u, v1r = (unsigned)r1 < 32u;
    int go0 = r0 << 5, go1 = r1 << 5;
    const __half hz = __ushort_as_half((unsigned short)0);

    float acc[2][8][4];
#pragma unroll
    for (int mt = 0; mt < 2; mt++)
#pragma unroll
        for (int j = 0; j < 8; j++)
#pragma unroll
            for (int q = 0; q < 4; q++) acc[mt][j][q] = 0.f;

    __half hq0[8], hq1[8];

#define LDG_B(chn) do { \
    int c0ch = (chn) * 8; \
    _Pragma("unroll") \
    for (int u = 0; u < 8; u++) { \
        int k2l = half * 8 + u; \
        int c = c0ch + (k2l >> 1); \
        const __half* xp = xmb + (c << 10) + ((k2l & 1) ? go1 : go0); \
        bool rv = (k2l & 1) ? v1r : v0r; \
        hq0[u] = (rv && vL) ? xp[cL] : hz; \
        hq1[u] = (rv && vR) ? xp[cR] : hz; \
    } } while (0)

#define CPA_A(chn, son) do { \
    _Pragma("unroll") \
    for (int r = 0; r < 2; r++) { \
        int idx = r * 256 + tid; \
        cpa16(sb + ((son) + AHO + idx * 4) * 4, WhF + (size_t)(chn) * 2048 + idx * 4); \
        cpa16(sb + ((son) + ALO + idx * 4) * 4, WlF + (size_t)(chn) * 2048 + idx * 4); \
    } } while (0)

#define ST_B(son) do { \
    _Pragma("unroll") \
    for (int u = 0; u < 8; u++) { \
        int k2l = half * 8 + u; \
        __half2 pk = __halves2half2(hq0[u], hq1[u]); \
        sm32[(son) + BHO + k2l * BSTRIDE + n] = *reinterpret_cast<uint32_t*>(&pk); \
    } } while (0)

    // prologue: tile 0 into stage 0
    CPA_A(0, 0u);
    CPA_COMMIT;
    LDG_B(0);
    ST_B(0u);
    CPA_WAIT0;
    __syncthreads();

    int mw = wid & 3;
    int n_ = (wid >> 2) * 64 + (lane >> 2);
    int kq = lane & 3;

    uint32_t so = 0;
    for (int ch = 0; ch < 64; ch++) {
        uint32_t son = so ^ STGU;
        if (ch < 63) {
            CPA_A(ch + 1, son);
            CPA_COMMIT;
            LDG_B(ch + 1);
        }

        // mma on stage so: (Ah + Al) x Bh, fragments via LDS.128
#pragma unroll
        for (int ks = 0; ks < 2; ks++) {
            int kr = ks * 8 + kq;
            uint32_t ah[2][4], al[2][4];
#pragma unroll
            for (int mt = 0; mt < 2; mt++) {
                uint32_t fo = ((mw * 2 + mt) * 2 + ks) * 128 + lane * 4;
                uint4 vh = *(uint4*)&sm32[so + AHO + fo];
                ah[mt][0] = vh.x; ah[mt][1] = vh.y; ah[mt][2] = vh.z; ah[mt][3] = vh.w;
                uint4 vl = *(uint4*)&sm32[so + ALO + fo];
                al[mt][0] = vl.x; al[mt][1] = vl.y; al[mt][2] = vl.z; al[mt][3] = vl.w;
            }
#pragma unroll
            for (int j = 0; j < 8; j++) {
                int nn = n_ + 8 * j;
                uint32_t bh0 = sm32[so + BHO + kr * BSTRIDE + nn];
                uint32_t bh1 = sm32[so + BHO + (kr + 4) * BSTRIDE + nn];
#pragma unroll
                for (int mt = 0; mt < 2; mt++) {
                    mma16816(acc[mt][j], ah[mt], bh0, bh1);
                    mma16816(acc[mt][j], al[mt], bh0, bh1);
                }
            }
        }

        if (ch < 63) ST_B(son);
        CPA_WAIT0;
        __syncthreads();
        so = son;
    }

    // Epilogue: demod + bias + noise + leaky relu, stride-2 phase scatter.
    const float* nz = noise + (size_t)b * 4096;
    int m_ = mw * 32 + (lane >> 2);
#pragma unroll
    for (int mt = 0; mt < 2; mt++) {
#pragma unroll
        for (int hh = 0; hh < 2; hh++) {
            int o = o0 + m_ + mt * 16 + hh * 8;
            float dd = g_d[b * 512 + o];
            float bo = bias[o];
            float* ob = out + (size_t)(b * 512 + o) * 4096;
#pragma unroll
            for (int j = 0; j < 8; j++) {
                int nc = (wid >> 2) * 64 + 8 * j + kq * 2;
                int npx = nt * 128 + nc;
                int ii = npx >> 5, jj = npx & 31;
                int Y = 2 * ii + pa;
                int X0 = 2 * jj + pbp;
                float v0 = dd * acc[mt][j][hh * 2]     + bo + nz[Y * 64 + X0];
                float v1 = dd * acc[mt][j][hh * 2 + 1] + bo + nz[Y * 64 + X0 + 2];
                v0 = fmaxf(v0, 0.2f * v0);
                v1 = fmaxf(v1, 0.2f * v1);
                ob[Y * 64 + X0]     = v0;
                ob[Y * 64 + X0 + 2] = v1;
            }
        }
    }
}

// ---------------------------------------------------------------------------
extern "C" void kernel_launch(void* const* d_in, const int* in_sizes, int n_in,
                              void* d_out, int out_size) {
    const float* x      = (const float*)d_in[0];
    const float* style  = (const float*)d_in[1];
    const float* noise  = (const float*)d_in[2];
    const float* conv_w = (const float*)d_in[3];
    const float* fc_w   = (const float*)d_in[4];
    const float* fc_b   = (const float*)d_in[5];
    const float* bias   = (const float*)d_in[6];
    float* out = (float*)d_out;

    cudaFuncSetAttribute(k_mma, cudaFuncAttributeMaxDynamicSharedMemorySize,
                         SMEM_BYTES);

    k_style<<<16, 256>>>(style, fc_w, fc_b);
    k_weights<<<1024, 256>>>(conv_w);
    k_xprep<<<4096, 256>>>(x);
    k_demod_acc<<<dim3(16, 8), 512>>>();
    k_fin<<<16, 256>>>();
    dim3 grid(8, 4, 32);
    k_mma<<<grid, 256, SMEM_BYTES>>>(noise, bias, out);
}

// round 13
// speedup vs baseline: 4.9392x; 1.4626x over previous
#include <cuda_runtime.h>
#include <cuda_fp16.h>
#include <cstdint>

// Problem constants
#define BB 8
#define CC 512
#define OO 512

// Scratch (device globals; no allocation allowed)
__device__ float g_s[BB * CC];              // style modulation s[b][c]
__device__ float g_d[BB * OO];              // demod d[b][o]
__device__ float g_w2t[CC * OO];            // sum sq weights, [c][o]
__device__ float g_part[16 * BB * OO];      // demod partials [cs][b][o]
__device__ uint32_t g_Wh32[4 * 1024 * 512]; // A hi, fragment-linear (see k_weights)
__device__ __half g_xmh[BB * CC * 1024];    // modulated input, fp16 [b][c][pix]

// ---------------------------------------------------------------------------
__device__ __forceinline__ uint32_t smem_u32(const void* p) {
    uint32_t a;
    asm("{ .reg .u64 t; cvta.to.shared.u64 t, %1; cvt.u32.u64 %0, t; }" : "=r"(a) : "l"(p));
    return a;
}
__device__ __forceinline__ void mma16816(float* d, const uint32_t* a,
                                         uint32_t b0, uint32_t b1) {
    asm volatile(
        "mma.sync.aligned.m16n8k16.row.col.f32.f16.f16.f32 "
        "{%0,%1,%2,%3}, {%4,%5,%6,%7}, {%8,%9}, {%0,%1,%2,%3};"
        : "+f"(d[0]), "+f"(d[1]), "+f"(d[2]), "+f"(d[3])
        : "r"(a[0]), "r"(a[1]), "r"(a[2]), "r"(a[3]), "r"(b0), "r"(b1));
}
__device__ __forceinline__ void cpa16(uint32_t dst, const void* src) {
    asm volatile("cp.async.ca.shared.global [%0], [%1], 16;" :: "r"(dst), "l"(src));
}
#define CPA_COMMIT asm volatile("cp.async.commit_group;" ::: "memory")
#define CPA_WAIT0  asm volatile("cp.async.wait_group 0;" ::: "memory")

// Fragment-linear A index: [ph][ot(4)][ch(64)][mw(4)][mt(2)][ks(2)][lane(32)][w(4)]
__device__ __forceinline__ size_t afrag_idx(int ph, int k2g, int o) {
    int ch = k2g >> 4, k2l = k2g & 15;
    int ot = o >> 7, om = o & 127;
    int mw = om >> 5, r32 = om & 31;
    int mt = r32 >> 4, r16 = r32 & 15;
    int wb = r16 >> 3, lrow = r16 & 7;
    int ks = k2l >> 3, k8 = k2l & 7;
    int kq = k8 & 3, wk = k8 >> 2;
    int lane = lrow * 4 + kq;
    int w = wk * 2 + wb;
    return ((((size_t)ph * 4 + ot) * 64 + ch) * 2048) +
           ((((mw * 2 + mt) * 2 + ks) * 32 + lane) * 4 + w);
}

// ---------------------------------------------------------------------------
// s[b][c] = fc_b[c] + sum_k style[b][k] * fc_w[c][k]
__global__ void k_style(const float* __restrict__ style,
                        const float* __restrict__ fc_w,
                        const float* __restrict__ fc_b) {
    int gid = blockIdx.x * blockDim.x + threadIdx.x;
    int b = gid >> 9, c = gid & 511;
    const float* srow = style + b * 512;
    const float* wrow = fc_w + c * 512;
    float acc = fc_b[c];
#pragma unroll 8
    for (int k = 0; k < 512; k++) acc += srow[k] * wrow[k];
    g_s[gid] = acc;
}

// ---------------------------------------------------------------------------
// xmh[b][c][pix] = fp16(x * (1+s))
__global__ void k_xprep(const float* __restrict__ x) {
    int gid = blockIdx.x * blockDim.x + threadIdx.x;  // 1,048,576: 4 pix each
    int pix4 = gid & 255;
    int bc = gid >> 8;
    float s = 1.f + g_s[bc];
    float4 v = *(const float4*)&x[((size_t)bc << 10) + pix4 * 4];
    __half2 h01 = __floats2half2_rn(v.x * s, v.y * s);
    __half2 h23 = __floats2half2_rn(v.z * s, v.w * s);
    uint2 pk = make_uint2(*reinterpret_cast<uint32_t*>(&h01),
                          *reinterpret_cast<uint32_t*>(&h23));
    *(uint2*)&g_xmh[((size_t)bc << 10) + pix4 * 4] = pk;
}

// ---------------------------------------------------------------------------
// Per (o,c): w2; phase-combined 2x2 weights as fp16 (single-rounded) written
// directly in mma-fragment-linear order (one LDS.128 per fragment in k_mma).
__global__ void k_weights(const float* __restrict__ conv_w) {
    int gid = blockIdx.x * blockDim.x + threadIdx.x;  // 262144
    int o = gid >> 9, c = gid & 511;                  // c fast -> dense reads
    const float* wp = conv_w + (size_t)(o * 512 + c) * 9;
    float w[9];
    float w2 = 0.f;
#pragma unroll
    for (int t = 0; t < 9; t++) { w[t] = wp[t]; w2 += w[t] * w[t]; }
    g_w2t[c * 512 + o] = w2;

    float r[2][2][3];
#pragma unroll
    for (int dx = 0; dx < 3; dx++) {
        r[0][0][dx] = w[0 + dx];
        r[0][1][dx] = w[3 + dx] + w[6 + dx];
        r[1][0][dx] = w[0 + dx] + w[3 + dx];
        r[1][1][dx] = w[6 + dx];
    }
#pragma unroll
    for (int a = 0; a < 2; a++)
#pragma unroll
        for (int pb = 0; pb < 2; pb++) {
            int ph = a * 2 + pb;
            float val[4];
#pragma unroll
            for (int p = 0; p < 2; p++)
#pragma unroll
                for (int q = 0; q < 2; q++) {
                    float v;
                    if (pb == 0) v = (q == 0) ? r[a][p][0] : (r[a][p][1] + r[a][p][2]);
                    else         v = (q == 0) ? (r[a][p][0] + r[a][p][1]) : r[a][p][2];
                    val[p * 2 + q] = v;
                }
            __half2 h01 = __floats2half2_rn(val[0], val[1]);
            __half2 h23 = __floats2half2_rn(val[2], val[3]);
            g_Wh32[afrag_idx(ph, 2 * c, o)]     = *reinterpret_cast<uint32_t*>(&h01);
            g_Wh32[afrag_idx(ph, 2 * c + 1, o)] = *reinterpret_cast<uint32_t*>(&h23);
        }
}

// ---------------------------------------------------------------------------
// Demod partials: block (cs, b), 512 threads (one per o); 32 c's per block.
__global__ void k_demod_acc() {
    int cs = blockIdx.x, b = blockIdx.y;
    int o = threadIdx.x;
    const float* sb = g_s + b * 512;
    float acc = 0.f;
#pragma unroll 8
    for (int u = 0; u < 32; u++) {
        int c = cs * 32 + u;
        float t = 1.f + sb[c];
        acc += g_w2t[c * 512 + o] * t * t;
    }
    g_part[(cs * BB + b) * 512 + o] = acc;
}
// d = rsqrt(sum partials + eps)
__global__ void k_fin() {
    int gid = blockIdx.x * blockDim.x + threadIdx.x;  // 4096: b*512+o
    int b = gid >> 9, o = gid & 511;
    float acc = 1e-8f;
#pragma unroll
    for (int cs = 0; cs < 16; cs++) acc += g_part[(cs * BB + b) * 512 + o];
    g_d[gid] = rsqrtf(acc);
}

// ---------------------------------------------------------------------------
// Main GEMM on mma.sync, single-term fp16 (Ah x Bh), fp32 accum.
// A fragment-linear via cp.async (LDS.128 fragment loads); B gathered fp16.
#define AHO 0
#define BHO 2048
#define BSTRIDE 136
#define STGU (BHO + 16 * BSTRIDE)   // 4224 u32 per stage
#define SMEM_BYTES (2 * STGU * 4)

__global__ void __launch_bounds__(256, 2)
k_mma(const float* __restrict__ noise,
      const float* __restrict__ bias, float* __restrict__ out) {
    extern __shared__ uint32_t sm32[];
    uint32_t sb = smem_u32(sm32);
    int tid = threadIdx.x;
    int lane = tid & 31, wid = tid >> 5;

    int z = blockIdx.z;
    int b = z >> 2, ph = z & 3;
    int pa = ph >> 1, pbp = ph & 1;
    int nt = blockIdx.x;
    int o0 = blockIdx.y * 128;

    const __half* xmb = g_xmh + ((size_t)b << 19);
    const uint32_t* WhF = g_Wh32 + (((size_t)ph * 4 + (o0 >> 7)) * 64) * 2048;

    // B-gather mapping: thread -> pixel n, k2-half
    int n = tid & 127, half = tid >> 7;
    int np = nt * 128 + n, i = np >> 5, jc = np & 31;
    int cL = jc + pbp - 1, cR = cL + 1;
    bool vL = (unsigned)cL < 32u, vR = (unsigned)cR < 32u;
    int r0 = i + pa - 1, r1 = r0 + 1;
    bool v0r = (unsigned)r0 < 32u, v1r = (unsigned)r1 < 32u;
    int go0 = r0 << 5, go1 = r1 << 5;
    const __half hz = __ushort_as_half((unsigned short)0);

    float acc[2][8][4];
#pragma unroll
    for (int mt = 0; mt < 2; mt++)
#pragma unroll
        for (int j = 0; j < 8; j++)
#pragma unroll
            for (int q = 0; q < 4; q++) acc[mt][j][q] = 0.f;

    __half hq0[8], hq1[8];

#define LDG_B(chn) do { \
    int c0ch = (chn) * 8; \
    _Pragma("unroll") \
    for (int u = 0; u < 8; u++) { \
        int k2l = half * 8 + u; \
        int c = c0ch + (k2l >> 1); \
        const __half* xp = xmb + (c << 10) + ((k2l & 1) ? go1 : go0); \
        bool rv = (k2l & 1) ? v1r : v0r; \
        hq0[u] = (rv && vL) ? xp[cL] : hz; \
        hq1[u] = (rv && vR) ? xp[cR] : hz; \
    } } while (0)

#define CPA_A(chn, son) do { \
    _Pragma("unroll") \
    for (int r = 0; r < 2; r++) { \
        int idx = r * 256 + tid; \
        cpa16(sb + ((son) + AHO + idx * 4) * 4, WhF + (size_t)(chn) * 2048 + idx * 4); \
    } } while (0)

#define ST_B(son) do { \
    _Pragma("unroll") \
    for (int u = 0; u < 8; u++) { \
        int k2l = half * 8 + u; \
        __half2 pk = __halves2half2(hq0[u], hq1[u]); \
        sm32[(son) + BHO + k2l * BSTRIDE + n] = *reinterpret_cast<uint32_t*>(&pk); \
    } } while (0)

    // prologue: tile 0 into stage 0
    CPA_A(0, 0u);
    CPA_COMMIT;
    LDG_B(0);
    ST_B(0u);
    CPA_WAIT0;
    __syncthreads();

    int mw = wid & 3;
    int n_ = (wid >> 2) * 64 + (lane >> 2);
    int kq = lane & 3;

    uint32_t so = 0;
    for (int ch = 0; ch < 64; ch++) {
        uint32_t son = so ^ STGU;
        if (ch < 63) {
            CPA_A(ch + 1, son);
            CPA_COMMIT;
            LDG_B(ch + 1);
        }

        // mma on stage so: Ah x Bh, A fragments via LDS.128
#pragma unroll
        for (int ks = 0; ks < 2; ks++) {
            int kr = ks * 8 + kq;
            uint32_t ah[2][4];
#pragma unroll
            for (int mt = 0; mt < 2; mt++) {
                uint32_t fo = ((mw * 2 + mt) * 2 + ks) * 128 + lane * 4;
                uint4 vh = *(uint4*)&sm32[so + AHO + fo];
                ah[mt][0] = vh.x; ah[mt][1] = vh.y; ah[mt][2] = vh.z; ah[mt][3] = vh.w;
            }
#pragma unroll
            for (int j = 0; j < 8; j++) {
                int nn = n_ + 8 * j;
                uint32_t bh0 = sm32[so + BHO + kr * BSTRIDE + nn];
                uint32_t bh1 = sm32[so + BHO + (kr + 4) * BSTRIDE + nn];
#pragma unroll
                for (int mt = 0; mt < 2; mt++)
                    mma16816(acc[mt][j], ah[mt], bh0, bh1);
            }
        }

        if (ch < 63) ST_B(son);
        CPA_WAIT0;
        __syncthreads();
        so = son;
    }

    // Epilogue: demod + bias + noise + leaky relu, stride-2 phase scatter.
    const float* nz = noise + (size_t)b * 4096;
    int m_ = mw * 32 + (lane >> 2);
#pragma unroll
    for (int mt = 0; mt < 2; mt++) {
#pragma unroll
        for (int hh = 0; hh < 2; hh++) {
            int o = o0 + m_ + mt * 16 + hh * 8;
            float dd = g_d[b * 512 + o];
            float bo = bias[o];
            float* ob = out + (size_t)(b * 512 + o) * 4096;
#pragma unroll
            for (int j = 0; j < 8; j++) {
                int nc = (wid >> 2) * 64 + 8 * j + kq * 2;
                int npx = nt * 128 + nc;
                int ii = npx >> 5, jj = npx & 31;
                int Y = 2 * ii + pa;
                int X0 = 2 * jj + pbp;
                float v0 = dd * acc[mt][j][hh * 2]     + bo + nz[Y * 64 + X0];
                float v1 = dd * acc[mt][j][hh * 2 + 1] + bo + nz[Y * 64 + X0 + 2];
                v0 = fmaxf(v0, 0.2f * v0);
                v1 = fmaxf(v1, 0.2f * v1);
                ob[Y * 64 + X0]     = v0;
                ob[Y * 64 + X0 + 2] = v1;
            }
        }
    }
}

// ---------------------------------------------------------------------------
extern "C" void kernel_launch(void* const* d_in, const int* in_sizes, int n_in,
                              void* d_out, int out_size) {
    const float* x      = (const float*)d_in[0];
    const float* style  = (const float*)d_in[1];
    const float* noise  = (const float*)d_in[2];
    const float* conv_w = (const float*)d_in[3];
    const float* fc_w   = (const float*)d_in[4];
    const float* fc_b   = (const float*)d_in[5];
    const float* bias   = (const float*)d_in[6];
    float* out = (float*)d_out;

    cudaFuncSetAttribute(k_mma, cudaFuncAttributeMaxDynamicSharedMemorySize,
                         SMEM_BYTES);

    k_style<<<16, 256>>>(style, fc_w, fc_b);
    k_weights<<<1024, 256>>>(conv_w);
    k_xprep<<<4096, 256>>>(x);
    k_demod_acc<<<dim3(16, 8), 512>>>();
    k_fin<<<16, 256>>>();
    dim3 grid(8, 4, 32);
    k_mma<<<grid, 256, SMEM_BYTES>>>(noise, bias, out);
}